// round 15
// baseline (speedup 1.0000x reference)
#include <cuda_runtime.h>
#include <cuda_bf16.h>

// VectorNet fused, round 14: layers 0/1 packed FFMA; layer 2 on warp-level
// mma.sync bf16x3 (D = Ah*Bh + Ah*Bl + Al*Bh, fp32 regs accumulate).
// (tcgen05 unavailable: harness PTX targets sm_103, not sm_103a.)
// Persistent blocks, 512 thr = two decoupled 256-thr halves, 2 polys/half/tile.
// B=32, NPOLY=256, VPP=64, L=32, PLEN=256

#define NB 32
#define NQUADS 2048
#define MAIN_GRID 148

typedef unsigned long long u64;
typedef unsigned int u32;

__device__ float g_agg[NB * 256 * 128];  // 4 MB scratch

#define FMA2(d, x, w) asm("fma.rn.f32x2 %0, %1, %2, %0;" : "+l"(d) : "l"(x), "l"(w))
#define PACK2(dst, f) asm("mov.b64 %0, {%1, %1};" : "=l"(dst) : "f"(f))
#define UNPACK2(lo, hi, v) asm("mov.b64 {%0, %1}, %2;" : "=f"(lo), "=f"(hi) : "l"(v))
// res = bf16x2 {lo=a, hi=b}
#define CVTBF2(res, a, b) asm("cvt.rn.bf16x2.f32 %0, %1, %2;" : "=r"(res) : "f"(b), "f"(a))

#define LDSM4(r0, r1, r2, r3, addr) \
    asm volatile("ldmatrix.sync.aligned.m8n8.x4.shared.b16 {%0,%1,%2,%3}, [%4];" \
        : "=r"(r0), "=r"(r1), "=r"(r2), "=r"(r3) : "r"(addr))
#define MMABF16(c, a0, a1, a2, a3, b0, b1) \
    asm volatile("mma.sync.aligned.m16n8k16.row.col.f32.bf16.bf16.f32 " \
        "{%0,%1,%2,%3},{%4,%5,%6,%7},{%8,%9},{%0,%1,%2,%3};" \
        : "+f"((c)[0]), "+f"((c)[1]), "+f"((c)[2]), "+f"((c)[3]) \
        : "r"(a0), "r"(a1), "r"(a2), "r"(a3), "r"(b0), "r"(b1))

// ---- smem layout ----
// bytes [0,18432):      B2 hi bf16, [n=128][k=64] pad to 144B rows
// bytes [18432,36864):  B2 lo
#define B2HI_B   0
#define B2LO_B   18432
// floats:
#define W0_F     9216
#define W1_F     10240
#define W2L_F    14336   /* W2 rows 64..127 fp32 (sterm2), 8192 floats */
#define G0_F     22528
#define BE0_F    22560
#define B0_F     22592
#define G1_F     22624
#define BE1_F    22688
#define B1_F     22752
#define G2_F     22816
#define BE2_F    22944
#define BI2_F    23072
#define HBASE_F  23232
#define HSTRIDE_F 11904
// per-half floats (rel. to half base):
//  x0 @0 (4608, LD36) | h0 @4608 (4608, LD36)
//  A2hi bytes @0 (18432, 144B rows) ; A2lo bytes @18432  [alias x0/h0]
//  scr @9216 (2048) ; agg0 @11264 (64) ; agg1 @11328 (128)
//  st1 @11456 (128) ; st2 @11584 (256)
#define SMEM_MAIN_B ((HBASE_F + 2 * HSTRIDE_F) * 4)   /* 188160 */

__device__ __forceinline__ void hbar(int hp) {
    asm volatile("bar.sync %0, 256;" :: "r"(hp + 1) : "memory");
}
__device__ __forceinline__ u32 to_smem_u32(const void* p) {
    u32 a;
    asm("{ .reg .u64 t; cvta.to.shared.u64 t, %1; cvt.u32.u64 %0, t; }" : "=r"(a) : "l"(p));
    return a;
}

// ---------------------------------------------------------------------------
// Layer 0: (128x32) = x0(128x32,LD36) @ W0 + b0, LN, ReLU -> h0 (LD36)
// ---------------------------------------------------------------------------
__device__ __forceinline__ void gemm0(
    const float* __restrict__ xs, float* __restrict__ hs,
    const float* __restrict__ Ws, const float* __restrict__ gs,
    const float* __restrict__ bes, const float* __restrict__ bias, int ltid)
{
    const int rg = ltid >> 2, cg = ltid & 3;
    const int r0 = rg * 2, c0 = cg * 8;
    u64 acc[2][4];
    {
        ulonglong2 s01 = *reinterpret_cast<const ulonglong2*>(bias + c0);
        ulonglong2 s23 = *reinterpret_cast<const ulonglong2*>(bias + c0 + 4);
#pragma unroll
        for (int i = 0; i < 2; i++) {
            acc[i][0] = s01.x; acc[i][1] = s01.y;
            acc[i][2] = s23.x; acc[i][3] = s23.y;
        }
    }
#pragma unroll 2
    for (int k0 = 0; k0 < 32; k0 += 4) {
        float xv[2][4];
#pragma unroll
        for (int i = 0; i < 2; i++) {
            float4 t = *reinterpret_cast<const float4*>(xs + (r0 + i) * 36 + k0);
            xv[i][0] = t.x; xv[i][1] = t.y; xv[i][2] = t.z; xv[i][3] = t.w;
        }
#pragma unroll
        for (int kk = 0; kk < 4; kk++) {
            ulonglong2 wA = *reinterpret_cast<const ulonglong2*>(Ws + (k0 + kk) * 32 + c0);
            ulonglong2 wB = *reinterpret_cast<const ulonglong2*>(Ws + (k0 + kk) * 32 + c0 + 4);
#pragma unroll
            for (int i = 0; i < 2; i++) {
                u64 xx; PACK2(xx, xv[i][kk]);
                FMA2(acc[i][0], xx, wA.x); FMA2(acc[i][1], xx, wA.y);
                FMA2(acc[i][2], xx, wB.x); FMA2(acc[i][3], xx, wB.y);
            }
        }
    }
#pragma unroll
    for (int i = 0; i < 2; i++) {
        float a[8];
#pragma unroll
        for (int j = 0; j < 4; j++) UNPACK2(a[2 * j], a[2 * j + 1], acc[i][j]);
        float s = 0.f, s2 = 0.f;
#pragma unroll
        for (int j = 0; j < 8; j++) { s += a[j]; s2 = fmaf(a[j], a[j], s2); }
#pragma unroll
        for (int o = 2; o > 0; o >>= 1) {
            s  += __shfl_xor_sync(0xffffffffu, s, o);
            s2 += __shfl_xor_sync(0xffffffffu, s2, o);
        }
        float mu = s * 0.03125f, var = fmaf(-mu, mu, s2 * 0.03125f);
        float rstd = rsqrtf(var + 1e-5f);
        float4 o1, o2;
        o1.x = fmaxf(fmaf((a[0]-mu)*rstd, gs[c0+0], bes[c0+0]), 0.f);
        o1.y = fmaxf(fmaf((a[1]-mu)*rstd, gs[c0+1], bes[c0+1]), 0.f);
        o1.z = fmaxf(fmaf((a[2]-mu)*rstd, gs[c0+2], bes[c0+2]), 0.f);
        o1.w = fmaxf(fmaf((a[3]-mu)*rstd, gs[c0+3], bes[c0+3]), 0.f);
        o2.x = fmaxf(fmaf((a[4]-mu)*rstd, gs[c0+4], bes[c0+4]), 0.f);
        o2.y = fmaxf(fmaf((a[5]-mu)*rstd, gs[c0+5], bes[c0+5]), 0.f);
        o2.z = fmaxf(fmaf((a[6]-mu)*rstd, gs[c0+6], bes[c0+6]), 0.f);
        o2.w = fmaxf(fmaf((a[7]-mu)*rstd, gs[c0+7], bes[c0+7]), 0.f);
        *reinterpret_cast<float4*>(hs + (r0 + i) * 36 + c0)     = o1;
        *reinterpret_cast<float4*>(hs + (r0 + i) * 36 + c0 + 4) = o2;
    }
}

// ---------------------------------------------------------------------------
// Layer 1: (128x64) = h0 @ W1 + st1(poly), LN, ReLU -> A2 bf16 hi/lo
// (144B rows) + col-max partials in scr[rg*64 + c].
// ---------------------------------------------------------------------------
__device__ __forceinline__ void gemm1_bf16(
    const float* __restrict__ xs, char* __restrict__ a2,
    const float* __restrict__ Ws, const float* __restrict__ gs,
    const float* __restrict__ bes, const float* __restrict__ st,
    float* __restrict__ scr, int ltid, int hp)
{
    const int rg = ltid >> 3, cg = ltid & 7;
    const int r0 = rg * 4, c0 = cg * 8;
    const float* sb = st + (rg >> 4) * 64;

    u64 acc[4][4];
    {
        ulonglong2 s01 = *reinterpret_cast<const ulonglong2*>(sb + c0);
        ulonglong2 s23 = *reinterpret_cast<const ulonglong2*>(sb + c0 + 4);
#pragma unroll
        for (int i = 0; i < 4; i++) {
            acc[i][0] = s01.x; acc[i][1] = s01.y;
            acc[i][2] = s23.x; acc[i][3] = s23.y;
        }
    }
#pragma unroll 2
    for (int k0 = 0; k0 < 32; k0 += 4) {
        float xv[4][4];
#pragma unroll
        for (int i = 0; i < 4; i++) {
            float4 t = *reinterpret_cast<const float4*>(xs + (r0 + i) * 36 + k0);
            xv[i][0] = t.x; xv[i][1] = t.y; xv[i][2] = t.z; xv[i][3] = t.w;
        }
#pragma unroll
        for (int kk = 0; kk < 4; kk++) {
            ulonglong2 wA = *reinterpret_cast<const ulonglong2*>(Ws + (k0 + kk) * 64 + c0);
            ulonglong2 wB = *reinterpret_cast<const ulonglong2*>(Ws + (k0 + kk) * 64 + c0 + 4);
#pragma unroll
            for (int i = 0; i < 4; i++) {
                u64 xx; PACK2(xx, xv[i][kk]);
                FMA2(acc[i][0], xx, wA.x); FMA2(acc[i][1], xx, wA.y);
                FMA2(acc[i][2], xx, wB.x); FMA2(acc[i][3], xx, wB.y);
            }
        }
    }

    hbar(hp);   // all reads of x0/h0 done before A2 overwrites them

    float mx[8];
#pragma unroll
    for (int j = 0; j < 8; j++) mx[j] = 0.f;

#pragma unroll
    for (int i = 0; i < 4; i++) {
        float a[8];
#pragma unroll
        for (int j = 0; j < 4; j++) UNPACK2(a[2 * j], a[2 * j + 1], acc[i][j]);
        float s = 0.f, s2 = 0.f;
#pragma unroll
        for (int j = 0; j < 8; j++) { s += a[j]; s2 = fmaf(a[j], a[j], s2); }
#pragma unroll
        for (int o = 4; o > 0; o >>= 1) {
            s  += __shfl_xor_sync(0xffffffffu, s, o);
            s2 += __shfl_xor_sync(0xffffffffu, s2, o);
        }
        float mu = s * 0.015625f, var = fmaf(-mu, mu, s2 * 0.015625f);
        float rstd = rsqrtf(var + 1e-5f);
        float v[8];
#pragma unroll
        for (int j = 0; j < 8; j++) {
            v[j] = fmaxf(fmaf((a[j]-mu)*rstd, gs[c0+j], bes[c0+j]), 0.f);
            mx[j] = fmaxf(mx[j], v[j]);
        }
        uint4 hi, lo;
        CVTBF2(hi.x, v[0], v[1]); CVTBF2(hi.y, v[2], v[3]);
        CVTBF2(hi.z, v[4], v[5]); CVTBF2(hi.w, v[6], v[7]);
        float r[8];
        r[0] = v[0] - __uint_as_float(hi.x << 16);
        r[1] = v[1] - __uint_as_float(hi.x & 0xFFFF0000u);
        r[2] = v[2] - __uint_as_float(hi.y << 16);
        r[3] = v[3] - __uint_as_float(hi.y & 0xFFFF0000u);
        r[4] = v[4] - __uint_as_float(hi.z << 16);
        r[5] = v[5] - __uint_as_float(hi.z & 0xFFFF0000u);
        r[6] = v[6] - __uint_as_float(hi.w << 16);
        r[7] = v[7] - __uint_as_float(hi.w & 0xFFFF0000u);
        CVTBF2(lo.x, r[0], r[1]); CVTBF2(lo.y, r[2], r[3]);
        CVTBF2(lo.z, r[4], r[5]); CVTBF2(lo.w, r[6], r[7]);
        u32 off = (u32)((r0 + i) * 144 + c0 * 2);
        *reinterpret_cast<uint4*>(a2 + off)         = hi;
        *reinterpret_cast<uint4*>(a2 + 18432 + off) = lo;
    }
#pragma unroll
    for (int j = 0; j < 8; j++) scr[rg * 64 + c0 + j] = mx[j];
}

// ---------------------------------------------------------------------------
__global__ void __launch_bounds__(512, 1)
vn_main_kernel(const float* __restrict__ data,
               const float* __restrict__ W0g, const float* __restrict__ b0g,
               const float* __restrict__ g0g, const float* __restrict__ be0g,
               const float* __restrict__ W1g, const float* __restrict__ b1g,
               const float* __restrict__ g1g, const float* __restrict__ be1g,
               const float* __restrict__ W2g, const float* __restrict__ b2g,
               const float* __restrict__ g2g, const float* __restrict__ be2g)
{
    extern __shared__ float sm[];
    char* smc = reinterpret_cast<char*>(sm);
    const u32 smb = to_smem_u32(sm);
    const int tid = threadIdx.x;
    const int hp = tid >> 8;
    const int ltid = tid & 255;
    const int lane = ltid & 31;
    const int wih = ltid >> 5;           // warp in half (0..7)

    float* hbf  = sm + HBASE_F + hp * HSTRIDE_F;
    char*  hbc  = smc + (HBASE_F + hp * HSTRIDE_F) * 4;
    float* x0   = hbf;
    float* h0   = hbf + 4608;
    float* scr  = hbf + 9216;
    float* agg0 = hbf + 11264;
    float* agg1 = hbf + 11328;
    float* st1  = hbf + 11456;
    float* st2  = hbf + 11584;

    // ---- stage weights (block-wide, once) ----
    for (int i = tid; i < 1024; i += 512) sm[W0_F + i] = W0g[i];
    for (int i = tid; i < 4096; i += 512) sm[W1_F + i] = W1g[i];
    for (int i = tid; i < 8192; i += 512) sm[W2L_F + i] = W2g[8192 + i];
    for (int i = tid; i < 8192; i += 512) {
        int n = i >> 6, k = i & 63;
        float f = W2g[k * 128 + n];           // B2 = W2top^T
        __nv_bfloat16 hb = __float2bfloat16(f);
        float hf = __bfloat162float(hb);
        __nv_bfloat16 lb = __float2bfloat16(f - hf);
        u32 off = (u32)(n * 144 + k * 2);
        *reinterpret_cast<__nv_bfloat16*>(smc + B2HI_B + off) = hb;
        *reinterpret_cast<__nv_bfloat16*>(smc + B2LO_B + off) = lb;
    }
    if (tid < 32)       { sm[G0_F+tid]=g0g[tid]; sm[BE0_F+tid]=be0g[tid]; sm[B0_F+tid]=b0g[tid]; }
    else if (tid < 96)  { int i=tid-32;  sm[G1_F+i]=g1g[i]; sm[BE1_F+i]=be1g[i]; sm[B1_F+i]=b1g[i]; }
    else if (tid < 224) { int i=tid-96;  sm[G2_F+i]=g2g[i]; sm[BE2_F+i]=be2g[i]; }
    else if (tid < 352) { int i=tid-224; sm[BI2_F+i]=b2g[i]; }
    __syncthreads();   // only block-wide sync; halves free-run after this

    // lane-invariant ldmatrix base addresses
    const u32 abase = smb + (u32)(HBASE_F + hp * HSTRIDE_F) * 4;
    const int g8 = lane >> 3, r8 = lane & 7;
    // A x4: [m0-7 k0-7][m8-15 k0-7][m0-7 k8-15][m8-15 k8-15]
    const u32 a_lane = abase + (u32)((wih * 16 + (g8 & 1) * 8 + r8) * 144 + (g8 >> 1) * 16);
    // B x4 (pair p): [nt0 k0][nt0 k8][nt1 k0][nt1 k8]
    const u32 b_lane = smb + B2HI_B + (u32)(((g8 >> 1) * 8 + r8) * 144 + (g8 & 1) * 16);

    // ---- initial x0 ----
    {
        const int quad = blockIdx.x;
        const int b = quad >> 6, qi = quad & 63;
        const float* base = data +
            ((size_t)b * 16385 + 1 + (size_t)(qi * 4 + hp * 2) * 64) * 32;
#pragma unroll
        for (int t = 0; t < 4; t++) {
            int e4 = ltid + t * 256;
            float4 v = ((const float4*)base)[e4];
            int r = e4 >> 3, kq = e4 & 7;
            if (kq == 7) v.w = 0.f;
            *reinterpret_cast<float4*>(x0 + r * 36 + kq * 4) = v;
        }
    }
    hbar(hp);

    for (int quad = blockIdx.x; quad < NQUADS; quad += MAIN_GRID) {
        const int b = quad >> 6, qi = quad & 63;
        const int poly0 = qi * 4 + hp * 2;

        // ---- layer 0 ----
        gemm0(x0, h0, sm + W0_F, sm + G0_F, sm + BE0_F, sm + B0_F, ltid);
        hbar(hp);
        {
            const int col = ltid & 31, ch = ltid >> 5;
            float m = 0.f;
#pragma unroll
            for (int r = 0; r < 16; r++) m = fmaxf(m, h0[(ch * 16 + r) * 36 + col]);
            scr[ch * 32 + col] = m;
        }
        hbar(hp);
        if (ltid < 64) {
            int poly = ltid >> 5, col = ltid & 31;
            float m = scr[(poly * 4) * 32 + col];
#pragma unroll
            for (int c = 1; c < 4; c++) m = fmaxf(m, scr[(poly * 4 + c) * 32 + col]);
            agg0[poly * 32 + col] = m;
        }
        hbar(hp);
        if (ltid < 128) {
            int poly = ltid >> 6, col = ltid & 63;
            float v = sm[B1_F + col];
#pragma unroll
            for (int k = 0; k < 32; k++)
                v = fmaf(agg0[poly * 32 + k], sm[W1_F + (32 + k) * 64 + col], v);
            st1[poly * 64 + col] = v;
        }
        hbar(hp);

        // ---- layer 1 (internal hbar; writes A2 hi/lo + scr partials) ----
        gemm1_bf16(h0, hbc, sm + W1_F, sm + G1_F, sm + BE1_F, st1, scr, ltid, hp);
        hbar(hp);

        // ---- agg1 + sterm2 ----
        if (ltid < 128) {
            int poly = ltid >> 6, col = ltid & 63;
            float m = scr[(poly * 16) * 64 + col];
#pragma unroll
            for (int i = 1; i < 16; i++) m = fmaxf(m, scr[(poly * 16 + i) * 64 + col]);
            agg1[poly * 64 + col] = m;
        }
        hbar(hp);
        {
            int poly = ltid >> 7, col = ltid & 127;
            float v = sm[BI2_F + col];
#pragma unroll 8
            for (int k = 0; k < 64; k++)
                v = fmaf(agg1[poly * 64 + k], sm[W2L_F + k * 128 + col], v);
            st2[ltid] = v;
        }
        // prefetch next x0 (hidden under MMA)
        int nq = quad + MAIN_GRID;
        if (nq >= NQUADS) nq = quad;
        const int nb = nq >> 6, nqi = nq & 63;
        const float* nbase = data +
            ((size_t)nb * 16385 + 1 + (size_t)(nqi * 4 + hp * 2) * 64) * 32;
        float4 xp[4];
#pragma unroll
        for (int t = 0; t < 4; t++) xp[t] = ((const float4*)nbase)[ltid + t * 256];
        hbar(hp);   // st2 visible

        // ---- layer 2: warp MMA, 16 rows x 128 cols per warp ----
        {
            float acc[16][4];
#pragma unroll
            for (int nt = 0; nt < 16; nt++)
#pragma unroll
                for (int j = 0; j < 4; j++) acc[nt][j] = 0.f;

#pragma unroll
            for (int ks = 0; ks < 4; ks++) {
                u32 ah0, ah1, ah2, ah3, al0, al1, al2, al3;
                LDSM4(ah0, ah1, ah2, ah3, a_lane + ks * 32);
                LDSM4(al0, al1, al2, al3, a_lane + 18432 + ks * 32);
#pragma unroll
                for (int p = 0; p < 8; p++) {
                    u32 bh0, bh1, bh2, bh3, bl0, bl1, bl2, bl3;
                    LDSM4(bh0, bh1, bh2, bh3, b_lane + p * 2304 + ks * 32);
                    LDSM4(bl0, bl1, bl2, bl3, b_lane + 18432 + p * 2304 + ks * 32);
                    MMABF16(acc[2*p],   ah0, ah1, ah2, ah3, bh0, bh1);
                    MMABF16(acc[2*p],   ah0, ah1, ah2, ah3, bl0, bl1);
                    MMABF16(acc[2*p],   al0, al1, al2, al3, bh0, bh1);
                    MMABF16(acc[2*p+1], ah0, ah1, ah2, ah3, bh2, bh3);
                    MMABF16(acc[2*p+1], ah0, ah1, ah2, ah3, bl2, bl3);
                    MMABF16(acc[2*p+1], al0, al1, al2, al3, bh2, bh3);
                }
            }

            // ---- epilogue: + sterm2, LN over 128 cols, ReLU, col-max ----
            const int poly = wih >> 2;
            const float* stp = st2 + poly * 128 + (lane & 3) * 2;
            float s_lo = 0.f, s2_lo = 0.f, s_hi = 0.f, s2_hi = 0.f;
#pragma unroll
            for (int nt = 0; nt < 16; nt++) {
                float2 sv = *reinterpret_cast<const float2*>(stp + nt * 8);
                acc[nt][0] += sv.x; acc[nt][1] += sv.y;
                acc[nt][2] += sv.x; acc[nt][3] += sv.y;
                s_lo += acc[nt][0] + acc[nt][1];
                s2_lo = fmaf(acc[nt][0], acc[nt][0], fmaf(acc[nt][1], acc[nt][1], s2_lo));
                s_hi += acc[nt][2] + acc[nt][3];
                s2_hi = fmaf(acc[nt][2], acc[nt][2], fmaf(acc[nt][3], acc[nt][3], s2_hi));
            }
#pragma unroll
            for (int o = 1; o <= 2; o <<= 1) {
                s_lo  += __shfl_xor_sync(0xffffffffu, s_lo,  o);
                s2_lo += __shfl_xor_sync(0xffffffffu, s2_lo, o);
                s_hi  += __shfl_xor_sync(0xffffffffu, s_hi,  o);
                s2_hi += __shfl_xor_sync(0xffffffffu, s2_hi, o);
            }
            float mu_lo = s_lo * 0.0078125f;
            float rstd_lo = rsqrtf(fmaf(-mu_lo, mu_lo, s2_lo * 0.0078125f) + 1e-5f);
            float mu_hi = s_hi * 0.0078125f;
            float rstd_hi = rsqrtf(fmaf(-mu_hi, mu_hi, s2_hi * 0.0078125f) + 1e-5f);

            const float* g2p  = sm + G2_F  + (lane & 3) * 2;
            const float* be2p = sm + BE2_F + (lane & 3) * 2;
#pragma unroll
            for (int nt = 0; nt < 16; nt++) {
                float2 gv = *reinterpret_cast<const float2*>(g2p + nt * 8);
                float2 bv = *reinterpret_cast<const float2*>(be2p + nt * 8);
                float m0 = fmaxf(
                    fmaxf(fmaf((acc[nt][0] - mu_lo) * rstd_lo, gv.x, bv.x), 0.f),
                    fmaxf(fmaf((acc[nt][2] - mu_hi) * rstd_hi, gv.x, bv.x), 0.f));
                float m1 = fmaxf(
                    fmaxf(fmaf((acc[nt][1] - mu_lo) * rstd_lo, gv.y, bv.y), 0.f),
                    fmaxf(fmaf((acc[nt][3] - mu_hi) * rstd_hi, gv.y, bv.y), 0.f));
#pragma unroll
                for (int o = 4; o <= 16; o <<= 1) {
                    m0 = fmaxf(m0, __shfl_xor_sync(0xffffffffu, m0, o));
                    m1 = fmaxf(m1, __shfl_xor_sync(0xffffffffu, m1, o));
                }
                if (lane < 4) {
                    float2 mm = {m0, m1};
                    *reinterpret_cast<float2*>(scr + wih * 128 + nt * 8 + lane * 2) = mm;
                }
            }
        }
        hbar(hp);

        // ---- finalize: g_agg + next x0 store ----
        {
            const int poly = ltid >> 7, c = ltid & 127;
            const int w0 = poly * 4;
            float m = fmaxf(fmaxf(scr[w0 * 128 + c], scr[(w0 + 1) * 128 + c]),
                            fmaxf(scr[(w0 + 2) * 128 + c], scr[(w0 + 3) * 128 + c]));
            g_agg[((size_t)(b * 256 + poly0 + poly)) * 128 + c] = m;
        }
#pragma unroll
        for (int t = 0; t < 4; t++) {
            int e4 = ltid + t * 256;
            int r = e4 >> 3, kq = e4 & 7;
            if (kq == 7) xp[t].w = 0.f;
            *reinterpret_cast<float4*>(x0 + r * 36 + kq * 4) = xp[t];
        }
        hbar(hp);
    }
}

// ---------------------------------------------------------------------------
// Attention kernel (unchanged).
// ---------------------------------------------------------------------------
__global__ void __launch_bounds__(512, 1)
vn_attn_kernel(const float* __restrict__ data,
               const float* __restrict__ Wq, const float* __restrict__ bq,
               const float* __restrict__ Wk,
               const float* __restrict__ Wv, const float* __restrict__ bv,
               float* __restrict__ out)
{
    extern __shared__ float sm[];
    float* Pb   = sm;
    float* q    = Pb + 33792;
    float* t    = q + 256;
    float* sc   = t + 128;
    float* w128 = sc + 256;
    float* red  = w128 + 128;
    float* part = red + 32;

    const int tid = threadIdx.x, lane = tid & 31, w = tid >> 5;
    const int b = blockIdx.x;

    const float* P = g_agg + (size_t)b * 256 * 128;
    for (int e4 = tid; e4 < 8192; e4 += 512) {
        int p = e4 >> 5, j4 = e4 & 31;
        *reinterpret_cast<float4*>(Pb + p * 132 + j4 * 4) = ((const float4*)P)[e4];
    }
    if (tid == 0) red[0] = data[(size_t)b * 16385 * 32];
    __syncthreads();
    const int aid = (int)red[0];

    {
        const int col = tid & 255, half = tid >> 8;
        const float* pr = Pb + aid * 132;
        float s = 0.f;
        for (int j = half * 64; j < half * 64 + 64; j++)
            s = fmaf(pr[j], Wq[j * 256 + col] + Wq[(j + 128) * 256 + col], s);
        part[half * 256 + col] = s;
    }
    __syncthreads();
    if (tid < 256) q[tid] = bq[tid] + part[tid] + part[256 + tid];
    __syncthreads();

    for (int jj = 0; jj < 8; jj++) {
        int j = w * 8 + jj;
        float a = 0.f;
#pragma unroll
        for (int m = 0; m < 8; m++) {
            int c = lane + m * 32;
            a = fmaf(Wk[j * 256 + c] + Wk[(j + 128) * 256 + c], q[c], a);
        }
#pragma unroll
        for (int o = 16; o > 0; o >>= 1) a += __shfl_xor_sync(0xffffffffu, a, o);
        if (lane == 0) t[j] = a;
    }
    __syncthreads();

    for (int pp = 0; pp < 16; pp++) {
        int p = w * 16 + pp;
        float a = 0.f;
#pragma unroll
        for (int m = 0; m < 4; m++) {
            int j = lane + m * 32;
            a = fmaf(Pb[p * 132 + j], t[j], a);
        }
#pragma unroll
        for (int o = 16; o > 0; o >>= 1) a += __shfl_xor_sync(0xffffffffu, a, o);
        if (lane == 0) sc[p] = a * 0.0625f;
    }
    __syncthreads();

    float v = 0.f, e = 0.f;
    if (tid < 256) {
        v = sc[tid];
        float mx = v;
#pragma unroll
        for (int o = 16; o > 0; o >>= 1) mx = fmaxf(mx, __shfl_xor_sync(0xffffffffu, mx, o));
        if (lane == 0) red[w] = mx;
    }
    __syncthreads();
    if (tid == 0) {
        float M = red[0];
        for (int i = 1; i < 8; i++) M = fmaxf(M, red[i]);
        red[8] = M;
    }
    __syncthreads();
    if (tid < 256) {
        e = __expf(v - red[8]);
        float se = e;
#pragma unroll
        for (int o = 16; o > 0; o >>= 1) se += __shfl_xor_sync(0xffffffffu, se, o);
        if (lane == 0) red[16 + w] = se;
    }
    __syncthreads();
    if (tid == 0) {
        float S = 0.f;
        for (int i = 0; i < 8; i++) S += red[16 + i];
        red[24] = 1.f / S;
    }
    __syncthreads();
    if (tid < 256) sc[tid] = e * red[24];
    __syncthreads();

    {
        const int col = tid & 127, seg = tid >> 7;
        float a = 0.f;
        for (int p = seg * 64; p < seg * 64 + 64; p++)
            a = fmaf(sc[p], Pb[p * 132 + col], a);
        part[seg * 128 + col] = a;
    }
    __syncthreads();
    if (tid < 128)
        w128[tid] = part[tid] + part[128 + tid] + part[256 + tid] + part[384 + tid];
    __syncthreads();

    {
        const int col = tid & 255, half = tid >> 8;
        float o = 0.f;
        for (int j = half * 64; j < half * 64 + 64; j++)
            o = fmaf(w128[j], Wv[j * 256 + col] + Wv[(j + 128) * 256 + col], o);
        part[half * 256 + col] = o;
    }
    __syncthreads();
    if (tid < 256) out[b * 256 + tid] = bv[tid] + part[tid] + part[256 + tid];
}

// ---------------------------------------------------------------------------
extern "C" void kernel_launch(void* const* d_in, const int* in_sizes, int n_in,
                              void* d_out, int out_size)
{
    const float* data = (const float*)d_in[0];
    const float* W0  = (const float*)d_in[1];
    const float* b0  = (const float*)d_in[2];
    const float* g0  = (const float*)d_in[3];
    const float* be0 = (const float*)d_in[4];
    const float* W1  = (const float*)d_in[5];
    const float* b1  = (const float*)d_in[6];
    const float* g1  = (const float*)d_in[7];
    const float* be1 = (const float*)d_in[8];
    const float* W2  = (const float*)d_in[9];
    const float* b2  = (const float*)d_in[10];
    const float* g2  = (const float*)d_in[11];
    const float* be2 = (const float*)d_in[12];
    const float* Wq  = (const float*)d_in[13];
    const float* bq  = (const float*)d_in[14];
    const float* Wk  = (const float*)d_in[15];
    // d_in[16] = bk: softmax-invariant, unused
    const float* Wv  = (const float*)d_in[17];
    const float* bv  = (const float*)d_in[18];
    float* out = (float*)d_out;

    const size_t smA = SMEM_MAIN_B;   // 188160 B
    const size_t smB = (size_t)(33792 + 256 + 128 + 256 + 128 + 32 + 512) * sizeof(float);
    cudaFuncSetAttribute(vn_main_kernel, cudaFuncAttributeMaxDynamicSharedMemorySize, (int)smA);
    cudaFuncSetAttribute(vn_attn_kernel, cudaFuncAttributeMaxDynamicSharedMemorySize, (int)smB);

    vn_main_kernel<<<MAIN_GRID, 512, smA>>>(data, W0, b0, g0, be0,
                                            W1, b1, g1, be1, W2, b2, g2, be2);
    vn_attn_kernel<<<NB, 512, smB>>>(data, Wq, bq, Wk, Wv, bv, out);
}